// round 2
// baseline (speedup 1.0000x reference)
#include <cuda_runtime.h>
#include <math.h>

#define Bn 8
#define An 100000
#define Cn 80
#define TOPN 1000
#define MAXOBJ 100

__device__ unsigned int  g_keys[Bn * An];
__device__ float4        g_topb[Bn * 1024];
__device__ float         g_tops[Bn * 1024];
__device__ float         g_topc[Bn * 1024];
__device__ float         g_area[Bn * 1024];
__device__ unsigned int  g_valid[Bn * 32];
__device__ unsigned int  g_mask[Bn * 32000];

// ---------- kernel 1: per-anchor class max -> key ----------
__global__ __launch_bounds__(256) void k_score(const float* __restrict__ cls) {
    int g = blockIdx.x * blockDim.x + threadIdx.x;
    if (g >= Bn * An) return;
    const float4* row = reinterpret_cast<const float4*>(cls) + (size_t)g * (Cn / 4);
    float4 v0 = row[0];
    float m0 = v0.x, m1 = v0.y, m2 = v0.z, m3 = v0.w;
#pragma unroll
    for (int q = 1; q < Cn / 4; ++q) {
        float4 v = row[q];
        m0 = fmaxf(m0, v.x); m1 = fmaxf(m1, v.y);
        m2 = fmaxf(m2, v.z); m3 = fmaxf(m3, v.w);
    }
    float m = fmaxf(fmaxf(m0, m1), fmaxf(m2, m3));
    g_keys[g] = (m > 0.05f) ? __float_as_uint(m) : 0u;
}

// ---------- kernel 2: exact top-1000 radix select + bitonic sort + gather ----------
__global__ __launch_bounds__(1024) void k_select(const float* __restrict__ cls,
                                                 const float4* __restrict__ reg,
                                                 const float4* __restrict__ anc) {
    int b = blockIdx.x, tid = threadIdx.x;
    __shared__ unsigned int hist[1024];
    __shared__ unsigned long long sk[1024];
    __shared__ unsigned long long s_pref;
    __shared__ int s_rank;
    __shared__ unsigned int s_cnt;
    const unsigned int* keys = g_keys + (size_t)b * An;

    unsigned long long prefix = 0ull;
    int rank = TOPN;
    for (int pass = 0; pass < 5; ++pass) {
        int shift = 40 - 10 * pass;
        hist[tid] = 0u;
        __syncthreads();
        for (int a = tid; a < An; a += 1024) {
            unsigned long long k =
                ((unsigned long long)keys[a] << 17) | (unsigned)(An - 1 - a);
            if ((k >> (shift + 10)) == prefix) {
                unsigned bucket = (unsigned)(k >> shift) & 1023u;
                unsigned msk = __match_any_sync(__activemask(), bucket);
                if ((tid & 31) == (__ffs(msk) - 1))
                    atomicAdd(&hist[bucket], (unsigned)__popc(msk));
            }
        }
        __syncthreads();
        if (tid < 32) {
            unsigned c[32]; unsigned gs = 0;
#pragma unroll
            for (int t = 0; t < 32; ++t) { c[t] = hist[tid * 32 + t]; gs += c[t]; }
            unsigned x = gs;
#pragma unroll
            for (int o = 1; o < 32; o <<= 1) {
                unsigned y = __shfl_down_sync(0xffffffffu, x, o);
                if (tid + o < 32) x += y;
            }
            unsigned above = x - gs;                 // keys in higher buckets
            if (above < (unsigned)rank && above + gs >= (unsigned)rank) {
                unsigned run = above; int sel = 0, nr = 0;
#pragma unroll
                for (int t = 31; t >= 0; --t) {
                    if (run + c[t] >= (unsigned)rank) { sel = t; nr = rank - (int)run; break; }
                    run += c[t];
                }
                s_pref = (prefix << 10) | (unsigned)(tid * 32 + sel);
                s_rank = nr;
            }
        }
        __syncthreads();
        prefix = s_pref; rank = s_rank;
        __syncthreads();
    }

    if (tid == 0) s_cnt = 0u;
    __syncthreads();
    for (int a = tid; a < An; a += 1024) {
        unsigned long long k =
            ((unsigned long long)keys[a] << 17) | (unsigned)(An - 1 - a);
        if (k >= prefix) {
            unsigned p = atomicAdd(&s_cnt, 1u);
            if (p < 1024u) sk[p] = k;
        }
    }
    __syncthreads();
    unsigned n = s_cnt;
    if ((unsigned)tid >= n) sk[tid] = 0ull;
    __syncthreads();

    // bitonic sort, descending
    for (int kk = 2; kk <= 1024; kk <<= 1) {
        for (int j = kk >> 1; j > 0; j >>= 1) {
            int ixj = tid ^ j;
            if (ixj > tid) {
                unsigned long long a0 = sk[tid], a1 = sk[ixj];
                bool dir = (tid & kk) == 0;
                if (dir ? (a0 < a1) : (a0 > a1)) { sk[tid] = a1; sk[ixj] = a0; }
            }
            __syncthreads();
        }
    }

    float s = 0.f;
    if (tid < TOPN) {
        unsigned long long k = sk[tid];
        int a = (An - 1) - (int)(k & 0x1FFFFull);
        s = __uint_as_float((unsigned)(k >> 17));

        const float4* c4 = reinterpret_cast<const float4*>(cls + ((size_t)b * An + a) * Cn);
        float best = -1.f; int bc = 0;
#pragma unroll
        for (int q = 0; q < Cn / 4; ++q) {
            float4 v = __ldg(c4 + q);
            if (v.x > best) { best = v.x; bc = 4 * q; }
            if (v.y > best) { best = v.y; bc = 4 * q + 1; }
            if (v.z > best) { best = v.z; bc = 4 * q + 2; }
            if (v.w > best) { best = v.w; bc = 4 * q + 3; }
        }

        float4 rg = __ldg(reg + (size_t)b * An + a);
        float4 an = __ldg(anc + (size_t)b * An + a);
        float aw  = __fsub_rn(an.z, an.x), ah = __fsub_rn(an.w, an.y);
        float acx = __fadd_rn(an.x, __fmul_rn(0.5f, aw));
        float acy = __fadd_rn(an.y, __fmul_rn(0.5f, ah));
        float pw  = __fmul_rn(expf(rg.z), aw);
        float ph  = __fmul_rn(expf(rg.w), ah);
        float pcx = __fadd_rn(__fmul_rn(rg.x, aw), acx);
        float pcy = __fadd_rn(__fmul_rn(rg.y, ah), acy);
        float hw  = __fmul_rn(0.5f, pw), hh = __fmul_rn(0.5f, ph);
        float x1 = truncf(__fsub_rn(pcx, hw));
        float y1 = truncf(__fsub_rn(pcy, hh));
        float x2 = truncf(__fadd_rn(pcx, hw));
        float y2 = truncf(__fadd_rn(pcy, hh));

        g_topb[b * 1024 + tid] = make_float4(x1, y1, x2, y2);
        g_tops[b * 1024 + tid] = s;
        g_topc[b * 1024 + tid] = (float)bc;
        g_area[b * 1024 + tid] = fmaxf(__fmul_rn(__fsub_rn(x2, x1), __fsub_rn(y2, y1)), 1e-4f);
    }
    bool v = (tid < TOPN) && (s > 0.05f);
    unsigned wm = __ballot_sync(0xffffffffu, v);
    if ((tid & 31) == 0) g_valid[b * 32 + (tid >> 5)] = wm;
}

// ---------- kernel 3: suppression bitmask (exact, division-free IoU >= 0.5) ----------
__global__ __launch_bounds__(256) void k_mask() {
    int b = blockIdx.y;
    __shared__ float4 sb[TOPN];
    __shared__ float  sa[TOPN];
    for (int t = threadIdx.x; t < TOPN; t += 256) {
        sb[t] = g_topb[b * 1024 + t];
        sa[t] = g_area[b * 1024 + t];
    }
    __syncthreads();
    int m = blockIdx.x * 256 + threadIdx.x;
    if (m >= 32000) return;
    int i = m >> 5, w = m & 31;
    float4 bi = sb[i]; float ai = sa[i];
    unsigned bits = 0;
    int j0 = w * 32;
    int jmax = min(TOPN - j0, 32);
    for (int t = 0; t < jmax; ++t) {
        int j = j0 + t;
        if (j <= i) continue;
        float4 bj = sb[j]; float aj = sa[j];
        float tlx = fmaxf(bi.x, bj.x), tly = fmaxf(bi.y, bj.y);
        float brx = fminf(bi.z, bj.z), bry = fminf(bi.w, bj.w);
        float sx = fmaxf(__fsub_rn(brx, tlx), 0.f), sy = fmaxf(__fsub_rn(bry, tly), 0.f);
        float inter = __fmul_rn(sx, sy);
        bool sup;
        if (ai >= 1.f && aj >= 1.f) {
            sup = (2.f * inter >= __fsub_rn(__fadd_rn(ai, aj), inter));
        } else {
            float uni = fmaxf(__fsub_rn(__fadd_rn(ai, aj), inter), 1e-4f);
            sup = (__fdiv_rn(inter, uni) >= 0.5f);
        }
        if (sup) bits |= (1u << t);
    }
    g_mask[b * 32000 + m] = bits;
}

// ---------- kernel 4: greedy NMS scan + compaction ----------
extern __shared__ unsigned int shm[];
__global__ __launch_bounds__(1024) void k_nms(float* __restrict__ out) {
    int b = blockIdx.x, tid = threadIdx.x;
    __shared__ unsigned int s_valid[32], s_kept[32];
    __shared__ int s_base[32];

    for (int i = tid; i < 32000; i += 1024) shm[i] = g_mask[b * 32000 + i];
    if (tid < 32) s_valid[tid] = g_valid[b * 32 + tid];
    if (tid < MAXOBJ) {
        out[b * MAXOBJ + tid] = -1.f;
        out[Bn * MAXOBJ + b * MAXOBJ + tid] = -1.f;
    }
    if (tid < MAXOBJ * 4) out[2 * Bn * MAXOBJ + b * MAXOBJ * 4 + tid] = 0.f;
    __syncthreads();

    if (tid < 32) {
        unsigned supp = ~s_valid[tid];
        for (int W = 0; W < 32; ++W) {
            unsigned cur = __shfl_sync(0xffffffffu, supp, W);
            int nb = min(TOPN - W * 32, 32);
            for (int t = 0; t < nb; ++t) {
                if (cur & (1u << t)) continue;
                int i = W * 32 + t;
                unsigned mrow = shm[i * 32 + tid];
                cur |= shm[i * 32 + W];
                supp |= mrow;
            }
        }
        unsigned kw = (~supp) & s_valid[tid];
        s_kept[tid] = kw;
        int c = __popc(kw), x = c;
#pragma unroll
        for (int o = 1; o < 32; o <<= 1) {
            int y = __shfl_up_sync(0xffffffffu, x, o);
            if (tid >= o) x += y;
        }
        s_base[tid] = x - c;
    }
    __syncthreads();

    if (tid < TOPN) {
        int w = tid >> 5, bt = tid & 31;
        unsigned kw = s_kept[w];
        if ((kw >> bt) & 1u) {
            int r = s_base[w] + __popc(kw & ((1u << bt) - 1u));
            if (r < MAXOBJ) {
                out[b * MAXOBJ + r] = g_tops[b * 1024 + tid];
                out[Bn * MAXOBJ + b * MAXOBJ + r] = g_topc[b * 1024 + tid];
                float4 bx = g_topb[b * 1024 + tid];
                float* ob = out + 2 * Bn * MAXOBJ + (b * MAXOBJ + r) * 4;
                ob[0] = bx.x; ob[1] = bx.y; ob[2] = bx.z; ob[3] = bx.w;
            }
        }
    }
}

extern "C" void kernel_launch(void* const* d_in, const int* in_sizes, int n_in,
                              void* d_out, int out_size) {
    const float*  cls = (const float*)d_in[0];
    const float4* reg = (const float4*)d_in[1];
    const float4* anc = (const float4*)d_in[2];
    float* out = (float*)d_out;

    cudaFuncSetAttribute(k_nms, cudaFuncAttributeMaxDynamicSharedMemorySize, 128000);

    k_score<<<(Bn * An + 255) / 256, 256>>>(cls);
    k_select<<<Bn, 1024>>>(cls, reg, anc);
    k_mask<<<dim3(125, Bn), 256>>>();
    k_nms<<<Bn, 1024, 128000>>>(out);
}

// round 3
// speedup vs baseline: 3.2399x; 3.2399x over previous
#include <cuda_runtime.h>
#include <math.h>

#define Bn 8
#define An 100000
#define Cn 80
#define TOPN 1000
#define MAXOBJ 100

__device__ unsigned int  g_keys[Bn * An];       // u = 0x3F800000 - score_bits (asc = better); 0xFFFFFFFF if filtered
__device__ float4        g_topb[Bn * 1024];
__device__ float         g_tops[Bn * 1024];
__device__ float         g_topc[Bn * 1024];
__device__ float         g_area[Bn * 1024];
__device__ unsigned int  g_valid[Bn * 32];
__device__ unsigned int  g_mask[Bn * 32000];

// ---------- kernel 1: per-anchor class max (4 threads per anchor, coalesced-ish) ----------
__global__ __launch_bounds__(256) void k_score(const float* __restrict__ cls) {
    int T = blockIdx.x * 256 + threadIdx.x;
    int a = T >> 2, r = T & 3;
    if (a >= Bn * An) return;
    const float4* p = reinterpret_cast<const float4*>(cls) + (size_t)a * 20;
    float m = -1.f;
#pragma unroll
    for (int k = 0; k < 5; ++k) {
        float4 v = __ldg(p + 4 * k + r);
        m = fmaxf(m, fmaxf(fmaxf(v.x, v.y), fmaxf(v.z, v.w)));
    }
    m = fmaxf(m, __shfl_xor_sync(0xffffffffu, m, 1));
    m = fmaxf(m, __shfl_xor_sync(0xffffffffu, m, 2));
    if (r == 0) {
        unsigned bits = __float_as_uint(m);
        unsigned u;
        if (m > 0.05f) u = (bits < 0x3F800000u) ? (0x3F800000u - bits) : 0u;
        else           u = 0xFFFFFFFFu;
        g_keys[a] = u;
    }
}

// ---------- kernel 2: histogram select + sort + gather/decode ----------
__global__ __launch_bounds__(1024) void k_select(const float* __restrict__ cls,
                                                 const float4* __restrict__ reg,
                                                 const float4* __restrict__ anc) {
    int b = blockIdx.x, tid = threadIdx.x;
    int lane = tid & 31, wid = tid >> 5;
    __shared__ unsigned hist[4096];
    __shared__ unsigned long long sk[1024];
    __shared__ unsigned wsum[32];
    __shared__ int s_cut;
    __shared__ unsigned s_tot, s_n;
    const unsigned* keys = g_keys + (size_t)b * An;

    for (int i = tid; i < 4096; i += 1024) hist[i] = 0u;
    if (tid == 0) { s_cut = -1; s_tot = 0u; s_n = 0u; }
    __syncthreads();

    // pass 1: histogram of u>>2 over buckets 0..4094 (>=4095 skipped)
    for (int a = tid; a < An; a += 1024) {
        unsigned u = keys[a];
        if (u < 16380u) atomicAdd(&hist[u >> 2], 1u);
    }
    __syncthreads();

    // prefix scan over 4096 buckets (4 per thread)
    unsigned h0 = hist[4 * tid], h1 = hist[4 * tid + 1],
             h2 = hist[4 * tid + 2], h3 = hist[4 * tid + 3];
    unsigned s = h0 + h1 + h2 + h3;
    unsigned x = s;
#pragma unroll
    for (int o = 1; o < 32; o <<= 1) {
        unsigned y = __shfl_up_sync(0xffffffffu, x, o);
        if (lane >= o) x += y;
    }
    if (lane == 31) wsum[wid] = x;
    __syncthreads();
    if (tid < 32) {
        unsigned v = wsum[tid];
#pragma unroll
        for (int o = 1; o < 32; o <<= 1) {
            unsigned y = __shfl_up_sync(0xffffffffu, v, o);
            if (tid >= o) v += y;
        }
        wsum[tid] = v;
    }
    __syncthreads();
    unsigned incl = x + (wid ? wsum[wid - 1] : 0u);
    unsigned excl = incl - s;
    if (excl < TOPN && incl >= TOPN) {
        int cut; unsigned c;
        if (excl + h0 >= TOPN)                { cut = 4 * tid;     c = excl + h0; }
        else if (excl + h0 + h1 >= TOPN)      { cut = 4 * tid + 1; c = excl + h0 + h1; }
        else if (excl + h0 + h1 + h2 >= TOPN) { cut = 4 * tid + 2; c = excl + h0 + h1 + h2; }
        else                                  { cut = 4 * tid + 3; c = excl + h0 + h1 + h2 + h3; }
        s_cut = cut; s_tot = c;
    }
    __syncthreads();

    bool fast = (s_cut >= 0) && (s_tot <= 1024u);
    if (fast) {
        unsigned ulimit = ((unsigned)s_cut + 1u) << 2;
        for (int a = tid; a < An; a += 1024) {
            unsigned u = keys[a];
            if (u < ulimit) {
                unsigned p = atomicAdd(&s_n, 1u);
                sk[p] = ((unsigned long long)u << 17) | (unsigned)a;
            }
        }
    } else {
        // fallback: exact bitwise radix select of TOPN-th smallest (u<<17|a), then compact <= it
        unsigned long long pref = 0ull;
        int rankNeed = TOPN;
        __shared__ unsigned s_c;
        for (int bit = 48; bit >= 0; --bit) {
            if (tid == 0) s_c = 0u;
            __syncthreads();
            unsigned c = 0;
            for (int a = tid; a < An; a += 1024) {
                unsigned long long k = ((unsigned long long)keys[a] << 17) | (unsigned)a;
                if ((k >> (bit + 1)) == pref && !((k >> bit) & 1ull)) c++;
            }
#pragma unroll
            for (int o = 16; o; o >>= 1) c += __shfl_down_sync(0xffffffffu, c, o);
            if (lane == 0) atomicAdd(&s_c, c);
            __syncthreads();
            unsigned C0 = s_c;
            if (rankNeed <= (int)C0) pref <<= 1;
            else { pref = (pref << 1) | 1ull; rankNeed -= (int)C0; }
            __syncthreads();
        }
        for (int a = tid; a < An; a += 1024) {
            unsigned long long k = ((unsigned long long)keys[a] << 17) | (unsigned)a;
            if (k <= pref) {
                unsigned p = atomicAdd(&s_n, 1u);
                sk[p] = k;
            }
        }
    }
    __syncthreads();
    unsigned n = s_n;
    if ((unsigned)tid >= n) sk[tid] = ~0ull;
    __syncthreads();

    // bitonic sort 1024 ascending (smaller key = higher score / smaller idx)
    for (int kk = 2; kk <= 1024; kk <<= 1) {
        for (int j = kk >> 1; j > 0; j >>= 1) {
            int ixj = tid ^ j;
            if (ixj > tid) {
                unsigned long long a0 = sk[tid], a1 = sk[ixj];
                bool asc = (tid & kk) == 0;
                if (asc ? (a0 > a1) : (a0 < a1)) { sk[tid] = a1; sk[ixj] = a0; }
            }
            __syncthreads();
        }
    }

    float sc = 0.f;
    if (tid < TOPN) {
        unsigned long long k = sk[tid];
        int a = (int)(k & 0x1FFFFull);
        unsigned u = (unsigned)(k >> 17);
        sc = (u >= 0x3F800000u) ? 0.f : __uint_as_float(0x3F800000u - u);

        const float4* c4 = reinterpret_cast<const float4*>(cls + ((size_t)b * An + a) * Cn);
        float best = -1.f; int bc = 0;
#pragma unroll
        for (int q = 0; q < Cn / 4; ++q) {
            float4 v = __ldg(c4 + q);
            if (v.x > best) { best = v.x; bc = 4 * q; }
            if (v.y > best) { best = v.y; bc = 4 * q + 1; }
            if (v.z > best) { best = v.z; bc = 4 * q + 2; }
            if (v.w > best) { best = v.w; bc = 4 * q + 3; }
        }

        float4 rg = __ldg(reg + (size_t)b * An + a);
        float4 an = __ldg(anc + (size_t)b * An + a);
        float aw  = __fsub_rn(an.z, an.x), ah = __fsub_rn(an.w, an.y);
        float acx = __fadd_rn(an.x, __fmul_rn(0.5f, aw));
        float acy = __fadd_rn(an.y, __fmul_rn(0.5f, ah));
        float pw  = __fmul_rn(expf(rg.z), aw);
        float ph  = __fmul_rn(expf(rg.w), ah);
        float pcx = __fadd_rn(__fmul_rn(rg.x, aw), acx);
        float pcy = __fadd_rn(__fmul_rn(rg.y, ah), acy);
        float hw  = __fmul_rn(0.5f, pw), hh = __fmul_rn(0.5f, ph);
        float x1 = truncf(__fsub_rn(pcx, hw));
        float y1 = truncf(__fsub_rn(pcy, hh));
        float x2 = truncf(__fadd_rn(pcx, hw));
        float y2 = truncf(__fadd_rn(pcy, hh));

        g_topb[b * 1024 + tid] = make_float4(x1, y1, x2, y2);
        g_tops[b * 1024 + tid] = sc;
        g_topc[b * 1024 + tid] = (float)bc;
        g_area[b * 1024 + tid] = fmaxf(__fmul_rn(__fsub_rn(x2, x1), __fsub_rn(y2, y1)), 1e-4f);
    } else {
        // pads: far-degenerate so any IoU test against them is false
        g_topb[b * 1024 + tid] = make_float4(1e9f, 1e9f, 1e9f, 1e9f);
        g_area[b * 1024 + tid] = 1e9f;
    }
    bool v = (tid < TOPN) && (sc > 0.05f);
    unsigned wm = __ballot_sync(0xffffffffu, v);
    if (lane == 0) g_valid[b * 32 + wid] = wm;
}

// ---------- kernel 3: suppression bitmask; warp = 32 rows, same word ----------
__global__ __launch_bounds__(256) void k_mask() {
    int b = blockIdx.y;
    __shared__ float4 sb[1024];
    __shared__ float  sa[1024];
    for (int t = threadIdx.x; t < 1024; t += 256) {
        sb[t] = g_topb[b * 1024 + t];
        sa[t] = g_area[b * 1024 + t];
    }
    __syncthreads();
    int m = blockIdx.x * 256 + threadIdx.x;   // 0..32767
    int w = m >> 10, i = m & 1023;
    if (i >= TOPN) return;
    unsigned bits = 0u;
    int jbase = w << 5;
    if (jbase + 31 > i) {
        float4 bi = sb[i]; float ai = sa[i];
#pragma unroll
        for (int t = 0; t < 32; ++t) {
            int j = jbase + t;
            float4 bj = sb[j]; float aj = sa[j];
            float tlx = fmaxf(bi.x, bj.x), tly = fmaxf(bi.y, bj.y);
            float brx = fminf(bi.z, bj.z), bry = fminf(bi.w, bj.w);
            float sx = fmaxf(__fsub_rn(brx, tlx), 0.f);
            float sy = fmaxf(__fsub_rn(bry, tly), 0.f);
            float inter = __fmul_rn(sx, sy);
            bool sup = (__fadd_rn(inter, inter) >= __fsub_rn(__fadd_rn(ai, aj), inter))
                       && (j > i);
            bits |= sup ? (1u << t) : 0u;
        }
    }
    g_mask[b * 32000 + i * 32 + w] = bits;
}

// ---------- kernel 4: greedy NMS (register-batched closure) + compaction ----------
extern __shared__ unsigned shm[];
__global__ __launch_bounds__(1024) void k_nms(float* __restrict__ out) {
    int b = blockIdx.x, tid = threadIdx.x;
    __shared__ unsigned s_kept[32];
    __shared__ int s_base[32];

    const uint4* src = reinterpret_cast<const uint4*>(g_mask + (size_t)b * 32000);
    uint4* dst = reinterpret_cast<uint4*>(shm);
    for (int i = tid; i < 8000; i += 1024) dst[i] = src[i];
    if (tid < MAXOBJ) {
        out[b * MAXOBJ + tid] = -1.f;
        out[Bn * MAXOBJ + b * MAXOBJ + tid] = -1.f;
    }
    if (tid < MAXOBJ * 4) out[2 * Bn * MAXOBJ + b * MAXOBJ * 4 + tid] = 0.f;
    __syncthreads();

    if (tid < 32) {
        int lane = tid;
        unsigned valid = g_valid[b * 32 + lane];
        unsigned supp = ~valid;
        for (int W = 0; W < 32; ++W) {
            unsigned rv[32];
#pragma unroll
            for (int t = 0; t < 32; ++t) {
                int row = W * 32 + t;
                rv[t] = (row < TOPN) ? shm[row * 32 + lane] : 0u;
            }
            unsigned cur = __shfl_sync(0xffffffffu, supp, W);
            if (lane == W) {
#pragma unroll
                for (int t = 0; t < 32; ++t) {
                    unsigned msk = (unsigned)((int)(cur << (31 - t)) >> 31);
                    cur |= rv[t] & ~msk;
                }
            }
            cur = __shfl_sync(0xffffffffu, cur, W);
#pragma unroll
            for (int t = 0; t < 32; ++t) {
                unsigned msk = (unsigned)((int)(cur << (31 - t)) >> 31);
                supp |= rv[t] & ~msk;
            }
        }
        unsigned kw = (~supp) & valid;
        s_kept[lane] = kw;
        int c = __popc(kw), x = c;
#pragma unroll
        for (int o = 1; o < 32; o <<= 1) {
            int y = __shfl_up_sync(0xffffffffu, x, o);
            if (lane >= o) x += y;
        }
        s_base[lane] = x - c;
    }
    __syncthreads();

    if (tid < TOPN) {
        int w = tid >> 5, bt = tid & 31;
        unsigned kw = s_kept[w];
        if ((kw >> bt) & 1u) {
            int r = s_base[w] + __popc(kw & ((1u << bt) - 1u));
            if (r < MAXOBJ) {
                out[b * MAXOBJ + r] = g_tops[b * 1024 + tid];
                out[Bn * MAXOBJ + b * MAXOBJ + r] = g_topc[b * 1024 + tid];
                float4 bx = g_topb[b * 1024 + tid];
                float* ob = out + 2 * Bn * MAXOBJ + (b * MAXOBJ + r) * 4;
                ob[0] = bx.x; ob[1] = bx.y; ob[2] = bx.z; ob[3] = bx.w;
            }
        }
    }
}

extern "C" void kernel_launch(void* const* d_in, const int* in_sizes, int n_in,
                              void* d_out, int out_size) {
    const float*  cls = (const float*)d_in[0];
    const float4* reg = (const float4*)d_in[1];
    const float4* anc = (const float4*)d_in[2];
    float* out = (float*)d_out;

    cudaFuncSetAttribute(k_nms, cudaFuncAttributeMaxDynamicSharedMemorySize, 128000);

    k_score<<<(Bn * An * 4 + 255) / 256, 256>>>(cls);
    k_select<<<Bn, 1024>>>(cls, reg, anc);
    k_mask<<<dim3(128, Bn), 256>>>();
    k_nms<<<Bn, 1024, 128000>>>(out);
}